// round 17
// baseline (speedup 1.0000x reference)
#include <cuda_runtime.h>

#define NN 1024
#define NMASK 1023
#define NQMASK 255     // float4s per row - 1
#define NH 512
#define TC 32          // subband cols per block
#define TRT 64         // output rows per CTA (two 32-row tiles)
#define TOTROWS 134    // tmp rows: 2*64 + 6
#define TSTRIDE 72     // tmp row stride in floats

// lo[j] = w[7-j]; hi[j] = (j odd) ? w[j] : -w[j] (sign folds into FFMA).
#define FMA_LO(v, j, s) (s) = fmaf((v), w[7 - (j)], (s))
#define FMA_HI(v, j, s) (s) = ((j) & 1) ? fmaf((v), w[(j)], (s)) \
                                        : fmaf((v), -w[(j)], (s))

// Horizontal filter for NTASKS = 16 * nrows tasks, tmp rows ROWOFF..ROWOFF+nrows-1.
// Uniform per-float4 periodic wrap; fully coalesced 16B-lane-stride loads.
template<int ROWOFF, int NTASKS>
__device__ __forceinline__ void horiz_rows(float* __restrict__ tmp,
                                           const float* __restrict__ xb,
                                           const float* w, int tid,
                                           int gr0, int gq0)
{
    #pragma unroll
    for (int it = 0; it < (NTASKS + 255) / 256; ++it) {
        int task = tid + it * 256;
        if (NTASKS % 256 == 0 || task < NTASKS) {
            int row  = ROWOFF + (task >> 4);
            int pair = task & 15;
            int gr   = (gr0 + row) & NMASK;
            const float4* rowp4 = (const float4*)(xb + (size_t)gr * NN);

            int q0 = gq0 + pair;
            float4 v0 = __ldg(rowp4 + ( q0      & NQMASK));
            float4 v1 = __ldg(rowp4 + ((q0 + 1) & NQMASK));
            float4 v2 = __ldg(rowp4 + ((q0 + 2) & NQMASK));
            float f[12] = { v0.x, v0.y, v0.z, v0.w,
                            v1.x, v1.y, v1.z, v1.w,
                            v2.x, v2.y, v2.z, v2.w };

            float sA0 = 0.f, sD0 = 0.f, sA1 = 0.f, sD1 = 0.f;
            #pragma unroll
            for (int j = 0; j < 8; ++j) {
                FMA_LO(f[1 + j], j, sA0);  FMA_HI(f[1 + j], j, sD0);
                FMA_LO(f[3 + j], j, sA1);  FMA_HI(f[3 + j], j, sD1);
            }
            *(float2*)&tmp[row * TSTRIDE + 2 * pair]      = make_float2(sA0, sA1);
            *(float2*)&tmp[row * TSTRIDE + 32 + 2 * pair] = make_float2(sD0, sD1);
        }
    }
}

// Vertical filter for one 32-row tile. tmpbase points at the tile's first tmp
// row; outputs rows r0o..r0o+31 of the subband grid. Warp-uniform:
// arr = A/D source half, q = row quarter; 8 output rows per thread.
__device__ __forceinline__ void vert_tile(const float* __restrict__ tmpbase,
                                          float* __restrict__ ob,   // out + b*NN*NN
                                          const float* w, int tid,
                                          int r0o, int c0)
{
    const int tx  = tid & 31;
    const int g   = tid >> 5;
    const int arr = g & 1;
    const int q   = g >> 1;

    float sL[8] = {0,0,0,0,0,0,0,0};
    float sH[8] = {0,0,0,0,0,0,0,0};

    const float* col = tmpbase + (16 * q) * TSTRIDE + 32 * arr + tx;
    #pragma unroll
    for (int i = 0; i < 22; ++i) {
        float v = col[i * TSTRIDE];
        #pragma unroll
        for (int m = 0; m < 8; ++m) {
            int j = i - 2 * m;
            if (j >= 0 && j < 8) {
                FMA_LO(v, j, sL[m]);
                FMA_HI(v, j, sH[m]);
            }
        }
    }

    float* obh = ob + (size_t)(arr * NH) * NN;   // arr=1 -> bottom half
    const int C = c0 + tx;
    #pragma unroll
    for (int m = 0; m < 8; ++m) {
        int R = r0o + 8 * q + m;
        obh[R * NN + C]      = sL[m];   // vertical low-pass  -> left cols
        obh[R * NN + C + NH] = sH[m];   // vertical high-pass -> right cols
    }
}

__global__ __launch_bounds__(256, 5)
void wav2d_kernel(const float* __restrict__ x,
                  const float* __restrict__ bmt,
                  float* __restrict__ out)
{
    __shared__ float tmp[TOTROWS * TSTRIDE];   // 38592 B

    const int tid = threadIdx.x;
    const int b  = blockIdx.z;
    const int r0 = blockIdx.y * TRT;           // first output row (of 64)
    const int c0 = blockIdx.x * TC;

    float w[8];
    #pragma unroll
    for (int j = 0; j < 8; ++j) w[j] = __ldg(&bmt[j]);

    const float* xb = x + (size_t)b * NN * NN;
    float*       ob = out + (size_t)b * NN * NN;
    const int gr0 = 2 * r0 - 3;          // first halo row (wrapped per-row)
    const int gq0 = (2 * c0 - 4) >> 2;   // first halo float4 index

    // Phase A: horizontal for tmp rows 0..69 (tile 1's window)
    horiz_rows<0, 70 * 16>(tmp, xb, w, tid, gr0, gq0);
    __syncthreads();

    // Phase B: vertical for tile 1 (reads tmp rows 0..69)
    //        + horizontal for tmp rows 70..133 (tile 2's remainder).
    // Disjoint tmp row ranges -> no barrier between the two halves.
    vert_tile(tmp, ob, w, tid, r0, c0);
    horiz_rows<70, 64 * 16>(tmp, xb, w, tid, gr0, gq0);
    __syncthreads();

    // Phase C: vertical for tile 2 (reads tmp rows 64..133; rows 64..69
    // were written in Phase A and never overwritten).
    vert_tile(tmp + 64 * TSTRIDE, ob, w, tid, r0 + 32, c0);
}

extern "C" void kernel_launch(void* const* d_in, const int* in_sizes, int n_in,
                              void* d_out, int out_size)
{
    const float* x   = (const float*)d_in[0];
    const float* bmt = (const float*)d_in[1];
    float* out = (float*)d_out;

    const int B = in_sizes[0] / (NN * NN);   // 32
    dim3 grid(NH / TC, NH / TRT, B);         // (16,8,32) = 4096 CTAs
    wav2d_kernel<<<grid, 256>>>(x, bmt, out);
}